// round 13
// baseline (speedup 1.0000x reference)
#include <cuda_runtime.h>

#define NN      64
#define NTYPES  4
#define NDESC   8
#define KMAX    8
#define RC      8.0f
#define PI_F    3.14159265358979323846f
#define MAX_ATOMS 32768

// packed[i] = (pos.x, pos.y, pos.z, bitcast(type))
__device__ float4 g_packed[MAX_ATOMS];

static __device__ __forceinline__ float fsqrt_approx(float x) {
    float y; asm("sqrt.approx.f32 %0, %1;" : "=f"(y) : "f"(x)); return y;
}
static __device__ __forceinline__ float fcos_approx(float x) {
    float y; asm("cos.approx.f32 %0, %1;" : "=f"(y) : "f"(x)); return y;
}
static __device__ __forceinline__ unsigned long long pack2(float lo, float hi) {
    unsigned long long r;
    asm("mov.b64 %0, {%1, %2};" : "=l"(r) : "f"(lo), "f"(hi));
    return r;
}
static __device__ __forceinline__ void fma2(unsigned long long& d,
                                            unsigned long long a,
                                            unsigned long long b) {
    asm("fma.rn.f32x2 %0, %1, %2, %0;" : "+l"(d) : "l"(a), "l"(b));
}
static __device__ __forceinline__ void unpack2(unsigned long long v, float& lo, float& hi) {
    asm("mov.b64 {%0, %1}, %2;" : "=f"(lo), "=f"(hi) : "l"(v));
}

__global__ void pack_kernel(const int* __restrict__ types,
                            const float* __restrict__ pos, int n)
{
    int i = blockIdx.x * blockDim.x + threadIdx.x;
    if (i < n) {
        float4 p;
        p.x = pos[i * 3 + 0];
        p.y = pos[i * 3 + 1];
        p.z = pos[i * 3 + 2];
        p.w = __int_as_float(types[i]);
        g_packed[i] = p;
    }
}

// R12 body (tied best 16.9us) retuned per the B300 multi-CTA-spread model:
// 128-thr blocks (4 warps x 4 atoms), 7 CTAs/SM at 70 regs -> 28 warps/SM,
// grid 1250 -> 1.18 waves. "#pragma unroll 1" on the half-loop keeps the
// front-batched LDG count (MLP_p1) at ~4-5 per iteration to bound cross-CTA
// L1tex queue contention (spr_max ~1.2 instead of ~1.6).
__global__ __launch_bounds__(128, 7) void radial_desc_kernel(
    const int*   __restrict__ nbr,
    const float* __restrict__ offs,
    const float* __restrict__ ctab,
    float*       __restrict__ out,
    int n_atoms)
{
    __shared__ float c_sh[NTYPES * NTYPES * NDESC * KMAX];  // 4 KB
    for (int i = threadIdx.x; i < NTYPES * NTYPES * NDESC * KMAX; i += blockDim.x)
        c_sh[i] = ctab[i];
    __syncthreads();

    const int lane = threadIdx.x & 31;
    const int warp = threadIdx.x >> 5;
    const int s    = lane & 7;    // lane within 8-lane group
    const int g    = lane >> 3;   // atom slot within warp

    const int atom = (blockIdx.x * 4 + warp) * 4 + g;
    const bool ok  = (atom < n_atoms);
    const int a    = ok ? atom : 0;

    const float4 pa = g_packed[a];
    const int    ti = __float_as_int(pa.w);

    unsigned long long Gp[16];     // Gp[t*4+i] = {G[t][2i], G[t][2i+1]}
    #pragma unroll
    for (int i = 0; i < 16; i++) Gp[i] = 0ull;

    const int4*   nb4 = reinterpret_cast<const int4*>(nbr)   + (long)a * 16 + s * 2;
    const float4* ob4 = reinterpret_cast<const float4*>(offs) + (long)a * 48 + s * 6;

    #pragma unroll 1
    for (int half = 0; half < 2; half++) {
        const int4 nv = nb4[half];
        const int nidx[4] = { nv.x, nv.y, nv.z, nv.w };

        const float4 f0 = ob4[half * 3 + 0];
        const float4 f1 = ob4[half * 3 + 1];
        const float4 f2 = ob4[half * 3 + 2];
        const float ox[4] = { f0.x, f0.w, f1.z, f2.y };
        const float oy[4] = { f0.y, f1.x, f1.w, f2.z };
        const float oz[4] = { f0.z, f1.y, f2.x, f2.w };

        // 4 independent gathers in flight
        float4 P[4];
        bool   vld[4];
        #pragma unroll
        for (int e = 0; e < 4; e++) {
            const int n = nidx[e];
            vld[e] = (n >= 0) && ok;
            P[e] = g_packed[vld[e] ? n : 0];
        }

        #pragma unroll
        for (int e = 0; e < 4; e++) {
            const float dx = P[e].x + ox[e] - pa.x;
            const float dy = P[e].y + oy[e] - pa.y;
            const float dz = P[e].z + oz[e] - pa.z;
            const int   tj = __float_as_int(P[e].w);

            const float r2 = dx * dx + dy * dy + dz * dz;
            const float r  = fsqrt_approx(r2);

            // h = 0.5 * fc; invalid edges fold to h = 0
            const float h = (vld[e] && (r < RC))
                          ? (0.25f * fcos_approx(r * (PI_F / RC)) + 0.25f)
                          : 0.0f;

            const float u  = r * (1.0f / RC) - 1.0f;
            const float x  = 2.0f * u * u - 1.0f;
            const float tw = x + x;
            const float T2 = tw * x  - 1.0f;
            const float T3 = tw * T2 - x;
            const float T4 = tw * T3 - T2;
            const float T5 = tw * T4 - T3;
            const float T6 = tw * T5 - T4;
            const float T7 = tw * T6 - T5;

            const unsigned long long V0 = pack2(1.0f, x);   // T0, T1
            const unsigned long long V1 = pack2(T2, T3);
            const unsigned long long V2 = pack2(T4, T5);
            const unsigned long long V3 = pack2(T6, T7);

            #pragma unroll
            for (int t = 0; t < 4; t++) {
                const float w0 = (tj == t) ? h : 0.0f;
                const unsigned long long W = pack2(w0, w0);
                fma2(Gp[t * 4 + 0], W, V0);
                fma2(Gp[t * 4 + 1], W, V1);
                fma2(Gp[t * 4 + 2], W, V2);
                fma2(Gp[t * 4 + 3], W, V3);
            }
        }
    }

    // unpack to v[32], v[t*8+k]
    float v[32];
    #pragma unroll
    for (int i = 0; i < 16; i++) unpack2(Gp[i], v[i * 2], v[i * 2 + 1]);

    // ---- halving-butterfly reduction of 32 values over the 8-lane group ----
    const bool hi4 = (s & 4) != 0;
    const bool hi2 = (s & 2) != 0;
    const bool hi1 = (s & 1) != 0;

    float v1[16];
    #pragma unroll
    for (int i = 0; i < 16; i++) {
        const float send = hi4 ? v[i] : v[i + 16];
        const float recv = __shfl_xor_sync(0xffffffffu, send, 4);
        v1[i] = (hi4 ? v[i + 16] : v[i]) + recv;
    }
    float v2[8];
    #pragma unroll
    for (int i = 0; i < 8; i++) {
        const float send = hi2 ? v1[i] : v1[i + 8];
        const float recv = __shfl_xor_sync(0xffffffffu, send, 2);
        v2[i] = (hi2 ? v1[i + 8] : v1[i]) + recv;
    }
    float v3[4];
    #pragma unroll
    for (int i = 0; i < 4; i++) {
        const float send = hi1 ? v2[i] : v2[i + 4];
        const float recv = __shfl_xor_sync(0xffffffffu, send, 1);
        v3[i] = (hi1 ? v2[i + 4] : v2[i]) + recv;
    }
    // lane s holds totals for t = ((s&4)>>1)|((s&2)>>1), k = (s&1)*4 + k'
    const int tl = ((s & 4) >> 1) | ((s & 2) >> 1);

    // F[t][k] = G[t][k] + G[t][0]  (folds the (T_k + 1) term; k=0 -> 2*G[t][0])
    const float g0 = __shfl_sync(0xffffffffu, v3[0], lane & ~1);
    const float F0 = v3[0] + g0;
    const float F1 = v3[1] + g0;
    const float F2 = v3[2] + g0;
    const float F3 = v3[3] + g0;

    const float4* c4p = reinterpret_cast<const float4*>(c_sh);
    const int base = ((ti * 4 + tl) * 8) * 2 + (s & 1);
    float p[8];
    #pragma unroll
    for (int d = 0; d < 8; d++) {
        const float4 c = c4p[base + d * 2];
        p[d] = c.x * F0 + c.y * F1 + c.z * F2 + c.w * F3;
    }

    float q[4];
    #pragma unroll
    for (int i = 0; i < 4; i++) {
        const float send = hi4 ? p[i] : p[i + 4];
        const float recv = __shfl_xor_sync(0xffffffffu, send, 4);
        q[i] = (hi4 ? p[i + 4] : p[i]) + recv;
    }
    float rr[2];
    #pragma unroll
    for (int i = 0; i < 2; i++) {
        const float send = hi2 ? q[i] : q[i + 2];
        const float recv = __shfl_xor_sync(0xffffffffu, send, 2);
        rr[i] = (hi2 ? q[i + 2] : q[i]) + recv;
    }
    {
        const float send = hi1 ? rr[0] : rr[1];
        const float recv = __shfl_xor_sync(0xffffffffu, send, 1);
        const float o = (hi1 ? rr[1] : rr[0]) + recv;
        if (ok) out[(long)atom * 8 + s] = o;   // 128B contiguous per warp
    }
}

extern "C" void kernel_launch(void* const* d_in, const int* in_sizes, int n_in,
                              void* d_out, int out_size) {
    const int*   types = (const int*)  d_in[0];
    const float* pos   = (const float*)d_in[1];
    const int*   nbr   = (const int*)  d_in[2];
    const float* offs  = (const float*)d_in[3];
    const float* ctab  = (const float*)d_in[4];
    float* out = (float*)d_out;

    int n_atoms = in_sizes[0];
    if (n_atoms > MAX_ATOMS) n_atoms = MAX_ATOMS;

    pack_kernel<<<(n_atoms + 255) / 256, 256>>>(types, pos, n_atoms);

    const int atoms_per_block = 16;               // 4 warps * 4 atoms
    const int grid = (n_atoms + atoms_per_block - 1) / atoms_per_block;
    radial_desc_kernel<<<grid, 128>>>(nbr, offs, ctab, out, n_atoms);
}

// round 14
// speedup vs baseline: 1.0467x; 1.0467x over previous
#include <cuda_runtime.h>

#define NN      64
#define NTYPES  4
#define NDESC   8
#define KMAX    8
#define RC      8.0f
#define PI_F    3.14159265358979323846f
#define MAX_ATOMS 32768

// packed[i] = (pos.x, pos.y, pos.z, bitcast(type))
__device__ float4 g_packed[MAX_ATOMS];

static __device__ __forceinline__ float fsqrt_approx(float x) {
    float y; asm("sqrt.approx.f32 %0, %1;" : "=f"(y) : "f"(x)); return y;
}
static __device__ __forceinline__ float fcos_approx(float x) {
    float y; asm("cos.approx.f32 %0, %1;" : "=f"(y) : "f"(x)); return y;
}
static __device__ __forceinline__ unsigned long long pack2(float lo, float hi) {
    unsigned long long r;
    asm("mov.b64 %0, {%1, %2};" : "=l"(r) : "f"(lo), "f"(hi));
    return r;
}
static __device__ __forceinline__ void fma2(unsigned long long& d,
                                            unsigned long long a,
                                            unsigned long long b) {
    asm("fma.rn.f32x2 %0, %1, %2, %0;" : "+l"(d) : "l"(a), "l"(b));
}
static __device__ __forceinline__ void unpack2(unsigned long long v, float& lo, float& hi) {
    asm("mov.b64 {%0, %1}, %2;" : "=f"(lo), "=f"(hi) : "l"(v));
}

__global__ void pack_kernel(const int* __restrict__ types,
                            const float* __restrict__ pos, int n)
{
    int i = blockIdx.x * blockDim.x + threadIdx.x;
    if (i < n) {
        float4 p;
        p.x = pos[i * 3 + 0];
        p.y = pos[i * 3 + 1];
        p.z = pos[i * 3 + 2];
        p.w = __int_as_float(types[i]);
        g_packed[i] = p;
    }
}

// Single-wave design: grid = 2 x #SM, every CTA resident from t=0 (no wave-2
// tail). Each CTA owns a contiguous ~66-atom range; each warp loops ~2 tiles
// of 4 atoms (8 lanes/atom) with register double-buffered prefetch of the next
// tile's nbr/offs streams. Body = R12 (fma.rn.f32x2 accumulate, 8-lane
// butterfly epilogue).
__global__ __launch_bounds__(256, 2) void radial_desc_kernel(
    const int*   __restrict__ nbr,
    const float* __restrict__ offs,
    const float* __restrict__ ctab,
    float*       __restrict__ out,
    int n_atoms, int n_cta)
{
    __shared__ float c_sh[NTYPES * NTYPES * NDESC * KMAX];  // 4 KB
    for (int i = threadIdx.x; i < NTYPES * NTYPES * NDESC * KMAX; i += blockDim.x)
        c_sh[i] = ctab[i];
    __syncthreads();

    const int c     = blockIdx.x;
    const int start = (int)(((long long)c * n_atoms) / n_cta);
    const int end   = (int)(((long long)(c + 1) * n_atoms) / n_cta);
    const int count = end - start;

    const int lane = threadIdx.x & 31;
    const int warp = threadIdx.x >> 5;
    const int s    = lane & 7;    // lane within 8-lane group
    const int g    = lane >> 3;   // atom slot within warp

    const bool hi4 = (s & 4) != 0;
    const bool hi2 = (s & 2) != 0;
    const bool hi1 = (s & 1) != 0;

    int base = warp * 4;
    if (base >= count) return;

    // ---- prefetch buffers (A = current, B = next) ----
    int4   nA0, nA1;
    float4 oA0, oA1, oA2, oA3, oA4, oA5;
    int aA;
    {
        const int gi = min(base + g, count - 1);
        aA = start + gi;
        const int4*   nb4 = reinterpret_cast<const int4*>(nbr)    + (long)aA * 16 + s * 2;
        const float4* ob4 = reinterpret_cast<const float4*>(offs) + (long)aA * 48 + s * 6;
        nA0 = nb4[0];  nA1 = nb4[1];
        oA0 = ob4[0];  oA1 = ob4[1];  oA2 = ob4[2];
        oA3 = ob4[3];  oA4 = ob4[4];  oA5 = ob4[5];
    }

    #pragma unroll 1
    while (true) {
        const int nbase = base + 32;
        const bool hasnext = nbase < count;

        // issue next tile's streaming loads before touching this tile's data
        int4   nB0, nB1;
        float4 oB0, oB1, oB2, oB3, oB4, oB5;
        int aB = aA;
        if (hasnext) {
            const int gi2 = min(nbase + g, count - 1);
            aB = start + gi2;
            const int4*   nb4 = reinterpret_cast<const int4*>(nbr)    + (long)aB * 16 + s * 2;
            const float4* ob4 = reinterpret_cast<const float4*>(offs) + (long)aB * 48 + s * 6;
            nB0 = nb4[0];  nB1 = nb4[1];
            oB0 = ob4[0];  oB1 = ob4[1];  oB2 = ob4[2];
            oB3 = ob4[3];  oB4 = ob4[4];  oB5 = ob4[5];
        }

        // ---- process current tile ----
        const bool ok = (base + g) < count;

        const float4 pa = g_packed[aA];
        const int    ti = __float_as_int(pa.w);

        unsigned long long Gp[16];     // Gp[t*4+i] = {G[t][2i], G[t][2i+1]}
        #pragma unroll
        for (int i = 0; i < 16; i++) Gp[i] = 0ull;

        const int4   nvv[2]  = { nA0, nA1 };
        const float4 off4[6] = { oA0, oA1, oA2, oA3, oA4, oA5 };

        #pragma unroll
        for (int half = 0; half < 2; half++) {
            const int4 nv = nvv[half];
            const int nidx[4] = { nv.x, nv.y, nv.z, nv.w };

            // 4 independent gathers in flight
            float4 P[4];
            bool   vld[4];
            #pragma unroll
            for (int e = 0; e < 4; e++) {
                const int n = nidx[e];
                vld[e] = (n >= 0);
                P[e] = g_packed[vld[e] ? n : 0];
            }

            const float4 f0 = off4[half * 3 + 0];
            const float4 f1 = off4[half * 3 + 1];
            const float4 f2 = off4[half * 3 + 2];
            const float ox[4] = { f0.x, f0.w, f1.z, f2.y };
            const float oy[4] = { f0.y, f1.x, f1.w, f2.z };
            const float oz[4] = { f0.z, f1.y, f2.x, f2.w };

            #pragma unroll
            for (int e = 0; e < 4; e++) {
                const float dx = P[e].x + ox[e] - pa.x;
                const float dy = P[e].y + oy[e] - pa.y;
                const float dz = P[e].z + oz[e] - pa.z;
                const int   tj = __float_as_int(P[e].w);

                const float r2 = dx * dx + dy * dy + dz * dz;
                const float r  = fsqrt_approx(r2);

                const float h = (vld[e] && (r < RC))
                              ? (0.25f * fcos_approx(r * (PI_F / RC)) + 0.25f)
                              : 0.0f;

                const float u  = r * (1.0f / RC) - 1.0f;
                const float x  = 2.0f * u * u - 1.0f;
                const float tw = x + x;
                const float T2 = tw * x  - 1.0f;
                const float T3 = tw * T2 - x;
                const float T4 = tw * T3 - T2;
                const float T5 = tw * T4 - T3;
                const float T6 = tw * T5 - T4;
                const float T7 = tw * T6 - T5;

                const unsigned long long V0 = pack2(1.0f, x);   // T0, T1
                const unsigned long long V1 = pack2(T2, T3);
                const unsigned long long V2 = pack2(T4, T5);
                const unsigned long long V3 = pack2(T6, T7);

                #pragma unroll
                for (int t = 0; t < 4; t++) {
                    const float w0 = (tj == t) ? h : 0.0f;
                    const unsigned long long W = pack2(w0, w0);
                    fma2(Gp[t * 4 + 0], W, V0);
                    fma2(Gp[t * 4 + 1], W, V1);
                    fma2(Gp[t * 4 + 2], W, V2);
                    fma2(Gp[t * 4 + 3], W, V3);
                }
            }
        }

        // unpack to v[32], v[t*8+k]
        float v[32];
        #pragma unroll
        for (int i = 0; i < 16; i++) unpack2(Gp[i], v[i * 2], v[i * 2 + 1]);

        // ---- halving-butterfly reduction over the 8-lane group ----
        float v1[16];
        #pragma unroll
        for (int i = 0; i < 16; i++) {
            const float send = hi4 ? v[i] : v[i + 16];
            const float recv = __shfl_xor_sync(0xffffffffu, send, 4);
            v1[i] = (hi4 ? v[i + 16] : v[i]) + recv;
        }
        float v2[8];
        #pragma unroll
        for (int i = 0; i < 8; i++) {
            const float send = hi2 ? v1[i] : v1[i + 8];
            const float recv = __shfl_xor_sync(0xffffffffu, send, 2);
            v2[i] = (hi2 ? v1[i + 8] : v1[i]) + recv;
        }
        float v3[4];
        #pragma unroll
        for (int i = 0; i < 4; i++) {
            const float send = hi1 ? v2[i] : v2[i + 4];
            const float recv = __shfl_xor_sync(0xffffffffu, send, 1);
            v3[i] = (hi1 ? v2[i + 4] : v2[i]) + recv;
        }
        const int tl = ((s & 4) >> 1) | ((s & 2) >> 1);

        const float g0 = __shfl_sync(0xffffffffu, v3[0], lane & ~1);
        const float F0 = v3[0] + g0;
        const float F1 = v3[1] + g0;
        const float F2 = v3[2] + g0;
        const float F3 = v3[3] + g0;

        const float4* c4p = reinterpret_cast<const float4*>(c_sh);
        const int cbase = ((ti * 4 + tl) * 8) * 2 + (s & 1);
        float p[8];
        #pragma unroll
        for (int d = 0; d < 8; d++) {
            const float4 cc = c4p[cbase + d * 2];
            p[d] = cc.x * F0 + cc.y * F1 + cc.z * F2 + cc.w * F3;
        }

        float q[4];
        #pragma unroll
        for (int i = 0; i < 4; i++) {
            const float send = hi4 ? p[i] : p[i + 4];
            const float recv = __shfl_xor_sync(0xffffffffu, send, 4);
            q[i] = (hi4 ? p[i + 4] : p[i]) + recv;
        }
        float rr[2];
        #pragma unroll
        for (int i = 0; i < 2; i++) {
            const float send = hi2 ? q[i] : q[i + 2];
            const float recv = __shfl_xor_sync(0xffffffffu, send, 2);
            rr[i] = (hi2 ? q[i + 2] : q[i]) + recv;
        }
        {
            const float send = hi1 ? rr[0] : rr[1];
            const float recv = __shfl_xor_sync(0xffffffffu, send, 1);
            const float o = (hi1 ? rr[1] : rr[0]) + recv;
            if (ok) out[(long)aA * 8 + s] = o;   // 128B contiguous per warp
        }

        if (!hasnext) break;

        // rotate buffers
        nA0 = nB0;  nA1 = nB1;
        oA0 = oB0;  oA1 = oB1;  oA2 = oB2;
        oA3 = oB3;  oA4 = oB4;  oA5 = oB5;
        aA = aB;
        base = nbase;
    }
}

extern "C" void kernel_launch(void* const* d_in, const int* in_sizes, int n_in,
                              void* d_out, int out_size) {
    const int*   types = (const int*)  d_in[0];
    const float* pos   = (const float*)d_in[1];
    const int*   nbr   = (const int*)  d_in[2];
    const float* offs  = (const float*)d_in[3];
    const float* ctab  = (const float*)d_in[4];
    float* out = (float*)d_out;

    int n_atoms = in_sizes[0];
    if (n_atoms > MAX_ATOMS) n_atoms = MAX_ATOMS;

    pack_kernel<<<(n_atoms + 255) / 256, 256>>>(types, pos, n_atoms);

    int n_sm = 148;
    cudaDeviceGetAttribute(&n_sm, cudaDevAttrMultiProcessorCount, 0);
    const int n_cta = 2 * n_sm;    // exactly the resident capacity -> one wave

    radial_desc_kernel<<<n_cta, 256>>>(nbr, offs, ctab, out, n_atoms, n_cta);
}

// round 15
// speedup vs baseline: 1.0626x; 1.0152x over previous
#include <cuda_runtime.h>

#define NN      64
#define NTYPES  4
#define NDESC   8
#define KMAX    8
#define RC      8.0f
#define PI_F    3.14159265358979323846f
#define MAX_ATOMS 32768

// packed[i] = (pos.x, pos.y, pos.z, bitcast(type))
__device__ float4 g_packed[MAX_ATOMS];
__device__ unsigned g_counter = 0;   // ticket counter for the in-kernel barrier

static __device__ __forceinline__ float fsqrt_approx(float x) {
    float y; asm("sqrt.approx.f32 %0, %1;" : "=f"(y) : "f"(x)); return y;
}
static __device__ __forceinline__ float fcos_approx(float x) {
    float y; asm("cos.approx.f32 %0, %1;" : "=f"(y) : "f"(x)); return y;
}
static __device__ __forceinline__ unsigned long long pack2(float lo, float hi) {
    unsigned long long r;
    asm("mov.b64 %0, {%1, %2};" : "=l"(r) : "f"(lo), "f"(hi));
    return r;
}
static __device__ __forceinline__ void fma2(unsigned long long& d,
                                            unsigned long long a,
                                            unsigned long long b) {
    asm("fma.rn.f32x2 %0, %1, %2, %0;" : "+l"(d) : "l"(a), "l"(b));
}
static __device__ __forceinline__ void unpack2(unsigned long long v, float& lo, float& hi) {
    asm("mov.b64 {%0, %1}, %2;" : "=f"(lo), "=f"(hi) : "l"(v));
}

// Fused single-wave persistent kernel. grid = 3 x #SM (all CTAs resident).
// Phase 0: cooperative pack of (pos,type) -> g_packed + global ticket barrier.
//   Replay-safe: graph launches serialize, so each launch's 456 tickets occupy
//   one aligned block [k*n_cta, (k+1)*n_cta); every CTA spins until the block
//   completes. All CTAs are resident (grid <= capacity), so no deadlock.
// Phase 1: R14 mainloop (fma.rn.f32x2 accumulate, 8-lane butterfly epilogue),
//   ~44 atoms/CTA -> max 2 tiles/warp (was 3), nbr-only register prefetch.
__global__ __launch_bounds__(256, 3) void radial_desc_kernel(
    const int*   __restrict__ types,
    const float* __restrict__ pos,
    const int*   __restrict__ nbr,
    const float* __restrict__ offs,
    const float* __restrict__ ctab,
    float*       __restrict__ out,
    int n_atoms, int n_cta)
{
    __shared__ float c_sh[NTYPES * NTYPES * NDESC * KMAX];  // 4 KB

    // ---- phase 0: pack + coeff stage ----
    for (int i = blockIdx.x * 256 + threadIdx.x; i < n_atoms; i += n_cta * 256) {
        float4 p;
        p.x = pos[i * 3 + 0];
        p.y = pos[i * 3 + 1];
        p.z = pos[i * 3 + 2];
        p.w = __int_as_float(types[i]);
        g_packed[i] = p;
    }
    for (int i = threadIdx.x; i < NTYPES * NTYPES * NDESC * KMAX; i += 256)
        c_sh[i] = ctab[i];

    __threadfence();            // publish packed stores before the ticket
    __syncthreads();
    if (threadIdx.x == 0) {
        const unsigned t = atomicAdd(&g_counter, 1u);
        const unsigned target = (t / (unsigned)n_cta + 1u) * (unsigned)n_cta;
        unsigned cur;
        do {
            asm volatile("ld.acquire.gpu.u32 %0, [%1];"
                         : "=r"(cur) : "l"(&g_counter) : "memory");
        } while (cur < target);
    }
    __syncthreads();            // whole CTA sees the completed pack

    // ---- phase 1: main work ----
    const int c     = blockIdx.x;
    const int start = (int)(((long long)c * n_atoms) / n_cta);
    const int end   = (int)(((long long)(c + 1) * n_atoms) / n_cta);
    const int count = end - start;

    const int lane = threadIdx.x & 31;
    const int warp = threadIdx.x >> 5;
    const int s    = lane & 7;    // lane within 8-lane group
    const int g    = lane >> 3;   // atom slot within warp

    const bool hi4 = (s & 4) != 0;
    const bool hi2 = (s & 2) != 0;
    const bool hi1 = (s & 1) != 0;

    int base = warp * 4;
    if (base >= count) return;

    // nbr-only prefetch (the gather-critical chain)
    int aA;
    int4 nA0, nA1;
    {
        const int gi = min(base + g, count - 1);
        aA = start + gi;
        const int4* nb4 = reinterpret_cast<const int4*>(nbr) + (long)aA * 16 + s * 2;
        nA0 = nb4[0];  nA1 = nb4[1];
    }

    #pragma unroll 1
    while (true) {
        const int nbase = base + 32;
        const bool hasnext = nbase < count;

        // prefetch next tile's nbr before processing this tile
        int aB = aA;
        int4 nB0, nB1;
        if (hasnext) {
            const int gi2 = min(nbase + g, count - 1);
            aB = start + gi2;
            const int4* nb4 = reinterpret_cast<const int4*>(nbr) + (long)aB * 16 + s * 2;
            nB0 = nb4[0];  nB1 = nb4[1];
        }

        const bool ok = (base + g) < count;

        const float4 pa = g_packed[aA];
        const int    ti = __float_as_int(pa.w);

        unsigned long long Gp[16];     // Gp[t*4+i] = {G[t][2i], G[t][2i+1]}
        #pragma unroll
        for (int i = 0; i < 16; i++) Gp[i] = 0ull;

        const float4* ob4 = reinterpret_cast<const float4*>(offs) + (long)aA * 48 + s * 6;
        const int4 nvv[2] = { nA0, nA1 };

        #pragma unroll
        for (int half = 0; half < 2; half++) {
            const int4 nv = nvv[half];
            const int nidx[4] = { nv.x, nv.y, nv.z, nv.w };

            // 4 independent gathers in flight
            float4 P[4];
            bool   vld[4];
            #pragma unroll
            for (int e = 0; e < 4; e++) {
                const int n = nidx[e];
                vld[e] = (n >= 0);
                P[e] = g_packed[vld[e] ? n : 0];
            }

            const float4 f0 = ob4[half * 3 + 0];
            const float4 f1 = ob4[half * 3 + 1];
            const float4 f2 = ob4[half * 3 + 2];
            const float ox[4] = { f0.x, f0.w, f1.z, f2.y };
            const float oy[4] = { f0.y, f1.x, f1.w, f2.z };
            const float oz[4] = { f0.z, f1.y, f2.x, f2.w };

            #pragma unroll
            for (int e = 0; e < 4; e++) {
                const float dx = P[e].x + ox[e] - pa.x;
                const float dy = P[e].y + oy[e] - pa.y;
                const float dz = P[e].z + oz[e] - pa.z;
                const int   tj = __float_as_int(P[e].w);

                const float r2 = dx * dx + dy * dy + dz * dz;
                const float r  = fsqrt_approx(r2);

                const float h = (vld[e] && (r < RC))
                              ? (0.25f * fcos_approx(r * (PI_F / RC)) + 0.25f)
                              : 0.0f;

                const float u  = r * (1.0f / RC) - 1.0f;
                const float x  = 2.0f * u * u - 1.0f;
                const float tw = x + x;
                const float T2 = tw * x  - 1.0f;
                const float T3 = tw * T2 - x;
                const float T4 = tw * T3 - T2;
                const float T5 = tw * T4 - T3;
                const float T6 = tw * T5 - T4;
                const float T7 = tw * T6 - T5;

                const unsigned long long V0 = pack2(1.0f, x);   // T0, T1
                const unsigned long long V1 = pack2(T2, T3);
                const unsigned long long V2 = pack2(T4, T5);
                const unsigned long long V3 = pack2(T6, T7);

                #pragma unroll
                for (int t = 0; t < 4; t++) {
                    const float w0 = (tj == t) ? h : 0.0f;
                    const unsigned long long W = pack2(w0, w0);
                    fma2(Gp[t * 4 + 0], W, V0);
                    fma2(Gp[t * 4 + 1], W, V1);
                    fma2(Gp[t * 4 + 2], W, V2);
                    fma2(Gp[t * 4 + 3], W, V3);
                }
            }
        }

        // unpack to v[32], v[t*8+k]
        float v[32];
        #pragma unroll
        for (int i = 0; i < 16; i++) unpack2(Gp[i], v[i * 2], v[i * 2 + 1]);

        // ---- halving-butterfly reduction over the 8-lane group ----
        float v1[16];
        #pragma unroll
        for (int i = 0; i < 16; i++) {
            const float send = hi4 ? v[i] : v[i + 16];
            const float recv = __shfl_xor_sync(0xffffffffu, send, 4);
            v1[i] = (hi4 ? v[i + 16] : v[i]) + recv;
        }
        float v2[8];
        #pragma unroll
        for (int i = 0; i < 8; i++) {
            const float send = hi2 ? v1[i] : v1[i + 8];
            const float recv = __shfl_xor_sync(0xffffffffu, send, 2);
            v2[i] = (hi2 ? v1[i + 8] : v1[i]) + recv;
        }
        float v3[4];
        #pragma unroll
        for (int i = 0; i < 4; i++) {
            const float send = hi1 ? v2[i] : v2[i + 4];
            const float recv = __shfl_xor_sync(0xffffffffu, send, 1);
            v3[i] = (hi1 ? v2[i + 4] : v2[i]) + recv;
        }
        const int tl = ((s & 4) >> 1) | ((s & 2) >> 1);

        const float g0 = __shfl_sync(0xffffffffu, v3[0], lane & ~1);
        const float F0 = v3[0] + g0;
        const float F1 = v3[1] + g0;
        const float F2 = v3[2] + g0;
        const float F3 = v3[3] + g0;

        const float4* c4p = reinterpret_cast<const float4*>(c_sh);
        const int cbase = ((ti * 4 + tl) * 8) * 2 + (s & 1);
        float p[8];
        #pragma unroll
        for (int d = 0; d < 8; d++) {
            const float4 cc = c4p[cbase + d * 2];
            p[d] = cc.x * F0 + cc.y * F1 + cc.z * F2 + cc.w * F3;
        }

        float q[4];
        #pragma unroll
        for (int i = 0; i < 4; i++) {
            const float send = hi4 ? p[i] : p[i + 4];
            const float recv = __shfl_xor_sync(0xffffffffu, send, 4);
            q[i] = (hi4 ? p[i + 4] : p[i]) + recv;
        }
        float rr[2];
        #pragma unroll
        for (int i = 0; i < 2; i++) {
            const float send = hi2 ? q[i] : q[i + 2];
            const float recv = __shfl_xor_sync(0xffffffffu, send, 2);
            rr[i] = (hi2 ? q[i + 2] : q[i]) + recv;
        }
        {
            const float send = hi1 ? rr[0] : rr[1];
            const float recv = __shfl_xor_sync(0xffffffffu, send, 1);
            const float o = (hi1 ? rr[1] : rr[0]) + recv;
            if (ok) out[(long)aA * 8 + s] = o;   // 128B contiguous per warp
        }

        if (!hasnext) break;

        nA0 = nB0;  nA1 = nB1;
        aA = aB;
        base = nbase;
    }
}

extern "C" void kernel_launch(void* const* d_in, const int* in_sizes, int n_in,
                              void* d_out, int out_size) {
    const int*   types = (const int*)  d_in[0];
    const float* pos   = (const float*)d_in[1];
    const int*   nbr   = (const int*)  d_in[2];
    const float* offs  = (const float*)d_in[3];
    const float* ctab  = (const float*)d_in[4];
    float* out = (float*)d_out;

    int n_atoms = in_sizes[0];
    if (n_atoms > MAX_ATOMS) n_atoms = MAX_ATOMS;

    int n_sm = 148;
    cudaDeviceGetAttribute(&n_sm, cudaDevAttrMultiProcessorCount, 0);
    const int n_cta = 3 * n_sm;    // <= resident capacity -> one wave, barrier-safe

    radial_desc_kernel<<<n_cta, 256>>>(types, pos, nbr, offs, ctab, out,
                                       n_atoms, n_cta);
}